// round 2
// baseline (speedup 1.0000x reference)
#include <cuda_runtime.h>
#include <math.h>

#define BATCH 64
#define NROW  307
#define NN    614
#define D     64

typedef unsigned long long ull;

// Scratch (device globals — allocation-free per harness rules)
__device__ float  g_Wh[(size_t)BATCH * NN * D];   // 10 MB
__device__ float  g_Wh1[BATCH * NN];
__device__ float  g_Wh2[BATCH * NN];
__device__ float2 g_w2z[BATCH * NN];              // {Wh2, 1/Z}
__device__ int    g_row_idx[NN * NN];
__device__ int    g_row_cnt[NN];
__device__ int    g_col_idx[NN * NN];
__device__ int    g_col_cnt[NN];

// ---- packed f32x2 helpers (FFMA2: only reachable via PTX) --------------
__device__ __forceinline__ ull pack2(float lo, float hi) {
    ull r; asm("mov.b64 %0, {%1,%2};" : "=l"(r) : "f"(lo), "f"(hi)); return r;
}
__device__ __forceinline__ void unpack2(float& lo, float& hi, ull v) {
    asm("mov.b64 {%0,%1}, %2;" : "=f"(lo), "=f"(hi) : "l"(v));
}
__device__ __forceinline__ void fma2(ull& d, ull a, ull b) {
    asm("fma.rn.f32x2 %0, %1, %2, %0;" : "+l"(d) : "l"(a), "l"(b));
}

// ---------------------------------------------------------------------------
// Kernel 0: build row-CSR and col-CSR of (adj > 0) via ballot compaction.
// ---------------------------------------------------------------------------
__global__ void k_csr(const float* __restrict__ adj) {
    const int r    = blockIdx.x;
    const int lane = threadIdx.x & 31;
    const int warp = threadIdx.x >> 5;
    if (warp == 0) {
        int cnt = 0;
        for (int m0 = 0; m0 < NN; m0 += 32) {
            int m = m0 + lane;
            float v = (m < NN) ? adj[r * NN + m] : 0.f;
            unsigned msk = __ballot_sync(0xffffffffu, v > 0.f);
            if (v > 0.f) {
                int pos = cnt + __popc(msk & ((1u << lane) - 1u));
                g_row_idx[r * NN + pos] = m;
            }
            cnt += __popc(msk);
        }
        if (lane == 0) g_row_cnt[r] = cnt;
    } else {
        int cnt = 0;
        for (int n0 = 0; n0 < NN; n0 += 32) {
            int n = n0 + lane;
            float v = (n < NN) ? adj[n * NN + r] : 0.f;
            unsigned msk = __ballot_sync(0xffffffffu, v > 0.f);
            if (v > 0.f) {
                int pos = cnt + __popc(msk & ((1u << lane) - 1u));
                g_col_idx[r * NN + pos] = n;
            }
            cnt += __popc(msk);
        }
        if (lane == 0) g_col_cnt[r] = cnt;
    }
}

// ---------------------------------------------------------------------------
// Kernel 1: Wh = concat(ht, h) @ W, plus Wh1 = Wh@a[:64], Wh2 = Wh@a[64:].
// 256 threads, 32 rows/block; thread = (row, 8 channels), FFMA2 inner loop.
// ---------------------------------------------------------------------------
__global__ __launch_bounds__(256) void k_wh(const float* __restrict__ h,
                                            const float* __restrict__ ht,
                                            const float* __restrict__ W,
                                            const float* __restrict__ a) {
    const int b     = blockIdx.y;
    const int rbase = blockIdx.x * 32;
    const int tid   = threadIdx.x;

    __shared__ __align__(16) float Ws[64 * 64];   // 16 KB
    __shared__ float xs[32 * 65];                 // padded: no bank conflicts
    __shared__ float as_[128];

    for (int k = tid; k < 4096; k += 256) Ws[k] = W[k];
    if (tid < 128) as_[tid] = a[tid];
    for (int k = tid; k < 2048; k += 256) {
        int r = k >> 6, i = k & 63;
        int gr = rbase + r;
        float v = 0.f;
        if (gr < NN)
            v = (gr < NROW) ? ht[((size_t)b * NROW + gr) * D + i]
                            : h [((size_t)b * NROW + gr - NROW) * D + i];
        xs[r * 65 + i] = v;
    }
    __syncthreads();

    const int r  = tid >> 3;
    const int c8 = (tid & 7) * 8;
    ull acc[4] = {0ull, 0ull, 0ull, 0ull};
#pragma unroll 4
    for (int i = 0; i < 64; i++) {
        float xv = xs[r * 65 + i];
        ull x2 = pack2(xv, xv);
        const ulonglong2* wp = (const ulonglong2*)&Ws[i * 64 + c8];
        ulonglong2 w01 = wp[0], w23 = wp[1];
        fma2(acc[0], x2, w01.x); fma2(acc[1], x2, w01.y);
        fma2(acc[2], x2, w23.x); fma2(acc[3], x2, w23.y);
    }

    float v[8];
    unpack2(v[0], v[1], acc[0]); unpack2(v[2], v[3], acc[1]);
    unpack2(v[4], v[5], acc[2]); unpack2(v[6], v[7], acc[3]);

    const int gr = rbase + r;
    if (gr < NN) {
        float* wr = &g_Wh[((size_t)b * NN + gr) * D + c8];
        *(float4*)(wr)     = make_float4(v[0], v[1], v[2], v[3]);
        *(float4*)(wr + 4) = make_float4(v[4], v[5], v[6], v[7]);
    }

    float p1 = 0.f, p2 = 0.f;
#pragma unroll
    for (int k = 0; k < 8; k++) {
        p1 = fmaf(v[k], as_[c8 + k], p1);
        p2 = fmaf(v[k], as_[64 + c8 + k], p2);
    }
#pragma unroll
    for (int off = 4; off > 0; off >>= 1) {
        p1 += __shfl_down_sync(0xffffffffu, p1, off, 8);
        p2 += __shfl_down_sync(0xffffffffu, p2, off, 8);
    }
    if ((tid & 7) == 0 && gr < NN) {
        g_Wh1[b * NN + gr] = p1;
        g_Wh2[b * NN + gr] = p2;
    }
}

// ---------------------------------------------------------------------------
// Kernel 2: column softmax denominators (axis=1), max-free (logits are O(10)).
// Packs {Wh2[m], 1/Z[m]} so k_out needs one scattered LDG.64 per neighbor.
// ---------------------------------------------------------------------------
__global__ void k_colstats() {
    const int b = blockIdx.y;
    const int m = blockIdx.x * blockDim.x + threadIdx.x;
    if (m >= NN) return;
    const int cnt = g_col_cnt[m];
    const float wh2m = g_Wh2[b * NN + m];
    const float* __restrict__ wh1 = &g_Wh1[b * NN];
    float Z = 0.f;
    for (int k = 0; k < cnt; k++) {
        int n = g_col_idx[m * NN + k];
        float s = wh1[n] + wh2m;
        float e = (s > 0.f) ? s : 0.2f * s;
        Z += __expf(e);
    }
    g_w2z[b * NN + m] = make_float2(wh2m, cnt ? 1.f / Z : 0.f);
}

// ---------------------------------------------------------------------------
// Kernel 3: h_prime[b,n,:] = sum_m w(n,m) * Wh[b,m,:]; concat + ELU.
// Half-warp per (b,n), 4 channels/lane via LDG.128 + FFMA2.
// All 8 pairs in a block share row n -> identical cnt, zero divergence.
// ---------------------------------------------------------------------------
__global__ __launch_bounds__(128) void k_out(float* __restrict__ out) {
    const int n    = blockIdx.x;
    const int tid  = threadIdx.x;
    const int pair = tid >> 4;        // 0..7
    const int l16  = tid & 15;
    const int b    = blockIdx.y * 8 + pair;
    const int cnt  = g_row_cnt[n];
    const float wh1n = g_Wh1[b * NN + n];

    __shared__ float2 stage[8][16];
    const char* whb = (const char*)g_Wh + (size_t)b * NN * 256 + l16 * 16;

    ull acc0 = 0ull, acc1 = 0ull;
    for (int k0 = 0; k0 < cnt; k0 += 16) {
        int k = k0 + l16;
        float w = 0.f; int off = 0;
        if (k < cnt) {
            int m = g_row_idx[n * NN + k];
            float2 wz = g_w2z[b * NN + m];
            float s = wh1n + wz.x;
            float e = (s > 0.f) ? s : 0.2f * s;
            w   = __expf(e) * wz.y;
            off = m << 8;
        }
        stage[pair][l16] = make_float2(w, __int_as_float(off));
        __syncwarp();
        const int lim = min(16, cnt - k0);
#pragma unroll 4
        for (int j = 0; j < lim; j++) {
            float2 p = stage[pair][j];
            ull w2 = pack2(p.x, p.x);
            ulonglong2 vv = *(const ulonglong2*)(whb + __float_as_int(p.y));
            fma2(acc0, w2, vv.x);
            fma2(acc1, w2, vv.y);
        }
        __syncwarp();
    }

    float o[4];
    unpack2(o[0], o[1], acc0); unpack2(o[2], o[3], acc1);
#pragma unroll
    for (int k = 0; k < 4; k++) o[k] = (o[k] > 0.f) ? o[k] : expm1f(o[k]);

    size_t ob = (n < NROW) ? (((size_t)b * NROW + n) * 128 + l16 * 4)
                           : (((size_t)b * NROW + (n - NROW)) * 128 + 64 + l16 * 4);
    *(float4*)(out + ob) = make_float4(o[0], o[1], o[2], o[3]);
}

// ---------------------------------------------------------------------------
extern "C" void kernel_launch(void* const* d_in, const int* in_sizes, int n_in,
                              void* d_out, int out_size) {
    const float* h   = (const float*)d_in[0];
    const float* ht  = (const float*)d_in[1];
    const float* W   = (const float*)d_in[2];
    const float* a   = (const float*)d_in[3];
    const float* adj = (const float*)d_in[4];
    float* out = (float*)d_out;

    k_csr<<<NN, 64>>>(adj);
    k_wh<<<dim3((NN + 31) / 32, BATCH), 256>>>(h, ht, W, a);
    k_colstats<<<dim3((NN + 127) / 128, BATCH), 128>>>();
    k_out<<<dim3(NN, BATCH / 8), 128>>>(out);
}

// round 3
// speedup vs baseline: 1.6348x; 1.6348x over previous
#include <cuda_runtime.h>
#include <cuda_fp16.h>
#include <math.h>

#define BATCH 64
#define NROW  307
#define NN    614
#define D     64

// Scratch (device globals — allocation-free per harness rules)
__device__ __half  g_Whh[(size_t)BATCH * NN * D];  // 5 MB, fp16 aggregation copy
__device__ float   g_Wh1[BATCH * NN];
__device__ float   g_Wh2[BATCH * NN];
__device__ float2  g_w2z[BATCH * NN];              // {Wh2, 1/Z}
__device__ int     g_row_idx[NN * NN];
__device__ int     g_row_cnt[NN];
__device__ int     g_col_idx[NN * NN];
__device__ int     g_col_cnt[NN];

// ---------------------------------------------------------------------------
// Kernel 0: row-CSR and col-CSR of (adj > 0) via ballot compaction.
// ---------------------------------------------------------------------------
__global__ void k_csr(const float* __restrict__ adj) {
    const int r    = blockIdx.x;
    const int lane = threadIdx.x & 31;
    const int warp = threadIdx.x >> 5;
    if (warp == 0) {
        int cnt = 0;
        for (int m0 = 0; m0 < NN; m0 += 32) {
            int m = m0 + lane;
            float v = (m < NN) ? adj[r * NN + m] : 0.f;
            unsigned msk = __ballot_sync(0xffffffffu, v > 0.f);
            if (v > 0.f) {
                int pos = cnt + __popc(msk & ((1u << lane) - 1u));
                g_row_idx[r * NN + pos] = m;
            }
            cnt += __popc(msk);
        }
        if (lane == 0) g_row_cnt[r] = cnt;
    } else {
        int cnt = 0;
        for (int n0 = 0; n0 < NN; n0 += 32) {
            int n = n0 + lane;
            float v = (n < NN) ? adj[n * NN + r] : 0.f;
            unsigned msk = __ballot_sync(0xffffffffu, v > 0.f);
            if (v > 0.f) {
                int pos = cnt + __popc(msk & ((1u << lane) - 1u));
                g_col_idx[r * NN + pos] = n;
            }
            cnt += __popc(msk);
        }
        if (lane == 0) g_col_cnt[r] = cnt;
    }
}

// ---------------------------------------------------------------------------
// Kernel 1 (R1-proven form): Wh = concat(ht,h)@W, Wh1 = Wh@a[:64],
// Wh2 = Wh@a[64:]. Block = 64 threads (one per channel), 8 rows per block.
// Wh stored in fp16 (aggregation only); logits stay fp32.
// ---------------------------------------------------------------------------
__global__ void k_wh(const float* __restrict__ h, const float* __restrict__ ht,
                     const float* __restrict__ W, const float* __restrict__ a) {
    const int b     = blockIdx.y;
    const int rbase = blockIdx.x * 8;
    const int tid   = threadIdx.x;   // channel c

    __shared__ float xs[8 * 64];
    for (int k = tid; k < 8 * 64; k += 64) {
        int rl = k >> 6, i = k & 63;
        int gr = rbase + rl;
        float v = 0.f;
        if (gr < NN) {
            v = (gr < NROW) ? ht[((size_t)b * NROW + gr) * D + i]
                            : h [((size_t)b * NROW + (gr - NROW)) * D + i];
        }
        xs[k] = v;
    }
    __syncthreads();

    float acc[8];
#pragma unroll
    for (int r = 0; r < 8; r++) acc[r] = 0.f;
    const int c = tid;
#pragma unroll 4
    for (int i = 0; i < D; i++) {
        float w = W[i * D + c];
#pragma unroll
        for (int r = 0; r < 8; r++) acc[r] = fmaf(xs[r * 64 + i], w, acc[r]);
    }

    const float a1 = a[c], a2 = a[D + c];
    __shared__ float red1[2][8], red2[2][8];
    const int lane = tid & 31, wrp = tid >> 5;
#pragma unroll
    for (int r = 0; r < 8; r++) {
        int gr = rbase + r;
        if (gr < NN) g_Whh[((size_t)b * NN + gr) * D + c] = __float2half_rn(acc[r]);
        float v1 = acc[r] * a1, v2 = acc[r] * a2;
#pragma unroll
        for (int off = 16; off > 0; off >>= 1) {
            v1 += __shfl_xor_sync(0xffffffffu, v1, off);
            v2 += __shfl_xor_sync(0xffffffffu, v2, off);
        }
        if (lane == 0) { red1[wrp][r] = v1; red2[wrp][r] = v2; }
    }
    __syncthreads();
    if (tid < 8) {
        int gr = rbase + tid;
        if (gr < NN) {
            g_Wh1[b * NN + gr] = red1[0][tid] + red1[1][tid];
            g_Wh2[b * NN + gr] = red2[0][tid] + red2[1][tid];
        }
    }
}

// ---------------------------------------------------------------------------
// Kernel 2: column softmax denominators (axis=1), max-free (validated R2).
// 8 lanes per (b,m) unit + shfl reduce; packs {Wh2, 1/Z}.
// ---------------------------------------------------------------------------
__global__ __launch_bounds__(128) void k_colstats() {
    const int tid  = threadIdx.x;
    const int unit = tid >> 3, lane = tid & 7;
    const int m    = blockIdx.x * 16 + unit;
    const int b    = blockIdx.y;
    if (m >= NN) return;
    const int cnt = g_col_cnt[m];
    const float wh2m = g_Wh2[b * NN + m];
    const float* __restrict__ wh1 = &g_Wh1[b * NN];
    float Z = 0.f;
    for (int k = lane; k < cnt; k += 8) {
        int n = g_col_idx[m * NN + k];
        float s = wh1[n] + wh2m;
        float e = (s > 0.f) ? s : 0.2f * s;   // LeakyReLU(0.2)
        Z += __expf(e);
    }
#pragma unroll
    for (int off = 4; off > 0; off >>= 1)
        Z += __shfl_xor_sync(0xffffffffu, Z, off, 8);
    if (lane == 0) g_w2z[b * NN + m] = make_float2(wh2m, 1.f / Z);
}

// ---------------------------------------------------------------------------
// Kernel 3: h_prime[b,n,:] = sum_m w(n,m) * Wh[b,m,:]; concat + ELU.
// 8 lanes per (b,n); lane owns 8 channels via one LDG.128 of fp16,
// fp32 accumulation. Block = 16 units (same n, 16 batches) -> no divergence.
// ---------------------------------------------------------------------------
__global__ __launch_bounds__(128) void k_out(float* __restrict__ out) {
    const int n    = blockIdx.x;
    const int tid  = threadIdx.x;
    const int unit = tid >> 3;        // 0..15
    const int lane = tid & 7;
    const int b    = blockIdx.y * 16 + unit;
    const int cnt  = g_row_cnt[n];
    const float wh1n = g_Wh1[b * NN + n];

    __shared__ float2 stage[16][8];
    const char* whb = (const char*)g_Whh + (size_t)b * NN * 128 + lane * 16;

    float acc[8];
#pragma unroll
    for (int k = 0; k < 8; k++) acc[k] = 0.f;

    for (int k0 = 0; k0 < cnt; k0 += 8) {
        int k = k0 + lane;
        float w = 0.f; int off = 0;
        if (k < cnt) {
            int m = g_row_idx[n * NN + k];
            float2 wz = g_w2z[b * NN + m];
            float s = wh1n + wz.x;
            float e = (s > 0.f) ? s : 0.2f * s;
            w   = __expf(e) * wz.y;
            off = m << 7;             // byte offset: m * 64 ch * 2B
        }
        stage[unit][lane] = make_float2(w, __int_as_float(off));
        __syncwarp();
        const int lim = min(8, cnt - k0);
#pragma unroll 8
        for (int j = 0; j < lim; j++) {
            float2 p = stage[unit][j];
            uint4 raw = *(const uint4*)(whb + __float_as_int(p.y));
            float2 f0 = __half22float2(*(const __half2*)&raw.x);
            float2 f1 = __half22float2(*(const __half2*)&raw.y);
            float2 f2 = __half22float2(*(const __half2*)&raw.z);
            float2 f3 = __half22float2(*(const __half2*)&raw.w);
            acc[0] = fmaf(p.x, f0.x, acc[0]); acc[1] = fmaf(p.x, f0.y, acc[1]);
            acc[2] = fmaf(p.x, f1.x, acc[2]); acc[3] = fmaf(p.x, f1.y, acc[3]);
            acc[4] = fmaf(p.x, f2.x, acc[4]); acc[5] = fmaf(p.x, f2.y, acc[5]);
            acc[6] = fmaf(p.x, f3.x, acc[6]); acc[7] = fmaf(p.x, f3.y, acc[7]);
        }
        __syncwarp();
    }

#pragma unroll
    for (int k = 0; k < 8; k++) acc[k] = (acc[k] > 0.f) ? acc[k] : expm1f(acc[k]);

    size_t ob = (n < NROW) ? (((size_t)b * NROW + n) * 128 + lane * 8)
                           : (((size_t)b * NROW + (n - NROW)) * 128 + 64 + lane * 8);
    *(float4*)(out + ob)     = make_float4(acc[0], acc[1], acc[2], acc[3]);
    *(float4*)(out + ob + 4) = make_float4(acc[4], acc[5], acc[6], acc[7]);
}

// ---------------------------------------------------------------------------
extern "C" void kernel_launch(void* const* d_in, const int* in_sizes, int n_in,
                              void* d_out, int out_size) {
    const float* h   = (const float*)d_in[0];
    const float* ht  = (const float*)d_in[1];
    const float* W   = (const float*)d_in[2];
    const float* a   = (const float*)d_in[3];
    const float* adj = (const float*)d_in[4];
    float* out = (float*)d_out;

    k_csr<<<NN, 64>>>(adj);
    k_wh<<<dim3((NN + 7) / 8, BATCH), 64>>>(h, ht, W, a);
    k_colstats<<<dim3((NN + 15) / 16, BATCH), 128>>>();
    k_out<<<dim3(NN, BATCH / 16), 128>>>(out);
}

// round 4
// speedup vs baseline: 1.7118x; 1.0471x over previous
#include <cuda_runtime.h>
#include <cuda_fp16.h>
#include <math.h>

#define BATCH 64
#define NROW  307
#define NN    614
#define D     64
#define XST   68   // smem tile stride (conflict-free for mma frag loads)

// Scratch (device globals — allocation-free per harness rules)
__device__ __align__(16) __half g_Whh[(size_t)BATCH * NN * D];  // 5 MB fp16 aggregation copy
__device__ float   g_Wh1[BATCH * NN];
__device__ float   g_Wh2[BATCH * NN];
__device__ float2  g_w2z[BATCH * NN];              // {Wh2, 1/Z}
__device__ int     g_row_idx[NN * NN];
__device__ int     g_row_cnt[NN];
__device__ int     g_col_idx[NN * NN];
__device__ int     g_col_cnt[NN];

__device__ __forceinline__ unsigned cvt_tf32(float f) {
    unsigned r; asm("cvt.rna.tf32.f32 %0, %1;" : "=r"(r) : "f"(f)); return r;
}
__device__ __forceinline__ void mma_tf32(float c[4], unsigned a0, unsigned a1,
                                         unsigned a2, unsigned a3,
                                         unsigned b0, unsigned b1) {
    asm("mma.sync.aligned.m16n8k8.row.col.f32.tf32.tf32.f32 "
        "{%0,%1,%2,%3},{%4,%5,%6,%7},{%8,%9},{%0,%1,%2,%3};"
        : "+f"(c[0]), "+f"(c[1]), "+f"(c[2]), "+f"(c[3])
        : "r"(a0), "r"(a1), "r"(a2), "r"(a3), "r"(b0), "r"(b1));
}

// ---------------------------------------------------------------------------
// Kernel 0: row-CSR + col-CSR of (adj>0). blockIdx.y=0: rows (coalesced per
// warp). blockIdx.y=1: columns via 32x33 smem-tile transpose (coalesced).
// ---------------------------------------------------------------------------
__global__ __launch_bounds__(1024) void k_csr(const float* __restrict__ adj) {
    const int tid  = threadIdx.x;
    const int lane = tid & 31;
    const int w    = tid >> 5;               // warp 0..31
    if (blockIdx.y == 0) {
        const int r = blockIdx.x * 32 + w;
        if (r >= NN) return;
        int cnt = 0;
        for (int m0 = 0; m0 < NN; m0 += 32) {
            int m = m0 + lane;
            float v = (m < NN) ? adj[r * NN + m] : 0.f;
            unsigned msk = __ballot_sync(0xffffffffu, v > 0.f);
            if (v > 0.f)
                g_row_idx[r * NN + cnt + __popc(msk & ((1u << lane) - 1u))] = m;
            cnt += __popc(msk);
        }
        if (lane == 0) g_row_cnt[r] = cnt;
    } else {
        __shared__ float tile[32][33];
        const int cbase = blockIdx.x * 32;
        const int c = cbase + w;              // this warp's column
        int cnt = 0;
        for (int n0 = 0; n0 < NN; n0 += 32) {
            int n = n0 + w, m = cbase + lane;
            tile[w][lane] = (n < NN && m < NN) ? adj[n * NN + m] : 0.f;
            __syncthreads();
            if (c < NN) {
                float v = tile[lane][w];
                unsigned msk = __ballot_sync(0xffffffffu, v > 0.f);
                if (v > 0.f)
                    g_col_idx[c * NN + cnt + __popc(msk & ((1u << lane) - 1u))] = n0 + lane;
                cnt += __popc(msk);
            }
            __syncthreads();
        }
        if (c < NN && lane == 0) g_col_cnt[c] = cnt;
    }
}

// ---------------------------------------------------------------------------
// Kernel 1: Wh = concat(ht,h)@W via tf32 mma (stored fp16), logits
// Wh1 = x@(W@a1), Wh2 = x@(W@a2) computed in exact fp32 from smem.
// Block = 128 threads (4 warps), 64 rows x 64 cols per block.
// ---------------------------------------------------------------------------
__global__ __launch_bounds__(128) void k_wh(const float* __restrict__ h,
                                            const float* __restrict__ ht,
                                            const float* __restrict__ W,
                                            const float* __restrict__ a) {
    const int b     = blockIdx.y;
    const int rbase = blockIdx.x * 64;
    const int tid   = threadIdx.x;

    __shared__ float xs[64 * XST];
    __shared__ float Ws[64 * XST];
    __shared__ float Wa[128];

    // Load W [64x64] and x tile [64x64] (float4, stride 68 keeps 16B align)
    for (int k = tid; k < 1024; k += 128) {
        int i = k >> 4, c4 = (k & 15) * 4;
        *(float4*)&Ws[i * XST + c4] = *(const float4*)&W[i * 64 + c4];
    }
    for (int k = tid; k < 1024; k += 128) {
        int r = k >> 4, c4 = (k & 15) * 4;
        int gr = rbase + r;
        float4 v = make_float4(0.f, 0.f, 0.f, 0.f);
        if (gr < NN) {
            const float* src = (gr < NROW) ? &ht[((size_t)b * NROW + gr) * D]
                                           : &h [((size_t)b * NROW + gr - NROW) * D];
            v = *(const float4*)(src + c4);
        }
        *(float4*)&xs[r * XST + c4] = v;
    }
    __syncthreads();

    // Wa[0:64] = W@a[:64], Wa[64:128] = W@a[64:]
    {
        int kk = tid & 63, which = tid >> 6;
        float s = 0.f;
        for (int c = 0; c < 64; c++)
            s = fmaf(Ws[kk * XST + c], a[which * 64 + c], s);
        Wa[which * 64 + kk] = s;
    }
    __syncthreads();

    // tf32 mma: warp owns 16 rows x 64 cols
    const int warp = tid >> 5, lane = tid & 31;
    const int g = lane >> 2, t4 = lane & 3;
    const int m0 = warp * 16;
    float acc[8][4];
#pragma unroll
    for (int nt = 0; nt < 8; nt++)
#pragma unroll
        for (int j = 0; j < 4; j++) acc[nt][j] = 0.f;

#pragma unroll
    for (int ks = 0; ks < 64; ks += 8) {
        unsigned A0 = cvt_tf32(xs[(m0 + g)     * XST + ks + t4]);
        unsigned A1 = cvt_tf32(xs[(m0 + g + 8) * XST + ks + t4]);
        unsigned A2 = cvt_tf32(xs[(m0 + g)     * XST + ks + t4 + 4]);
        unsigned A3 = cvt_tf32(xs[(m0 + g + 8) * XST + ks + t4 + 4]);
#pragma unroll
        for (int nt = 0; nt < 8; nt++) {
            unsigned B0 = cvt_tf32(Ws[(ks + t4)     * XST + nt * 8 + g]);
            unsigned B1 = cvt_tf32(Ws[(ks + t4 + 4) * XST + nt * 8 + g]);
            mma_tf32(acc[nt], A0, A1, A2, A3, B0, B1);
        }
    }

    // Store Wh as fp16
#pragma unroll
    for (int nt = 0; nt < 8; nt++) {
        int col = nt * 8 + t4 * 2;
        int r0 = rbase + m0 + g, r1 = r0 + 8;
        __half2 h0 = __floats2half2_rn(acc[nt][0], acc[nt][1]);
        __half2 h1 = __floats2half2_rn(acc[nt][2], acc[nt][3]);
        if (r0 < NN) *(__half2*)&g_Whh[((size_t)b * NN + r0) * D + col] = h0;
        if (r1 < NN) *(__half2*)&g_Whh[((size_t)b * NN + r1) * D + col] = h1;
    }

    // Exact fp32 logits
    {
        int r = tid & 63, which = tid >> 6;
        float s = 0.f;
#pragma unroll 4
        for (int k2 = 0; k2 < 64; k2++)
            s = fmaf(xs[r * XST + k2], Wa[which * 64 + k2], s);
        int gr = rbase + r;
        if (gr < NN) {
            if (which == 0) g_Wh1[b * NN + gr] = s;
            else            g_Wh2[b * NN + gr] = s;
        }
    }
}

// ---------------------------------------------------------------------------
// Kernel 2: column softmax denominators (axis=1), max-free (validated).
// 8 lanes per (b,m) + shfl reduce; packs {Wh2, 1/Z}.
// ---------------------------------------------------------------------------
__global__ __launch_bounds__(128) void k_colstats() {
    const int tid  = threadIdx.x;
    const int unit = tid >> 3, lane = tid & 7;
    const int m    = blockIdx.x * 16 + unit;
    const int b    = blockIdx.y;
    if (m >= NN) return;
    const int cnt = g_col_cnt[m];
    const float wh2m = g_Wh2[b * NN + m];
    const float* __restrict__ wh1 = &g_Wh1[b * NN];
    float Z = 0.f;
    for (int k = lane; k < cnt; k += 8) {
        int n = g_col_idx[m * NN + k];
        float s = wh1[n] + wh2m;
        float e = (s > 0.f) ? s : 0.2f * s;   // LeakyReLU(0.2)
        Z += __expf(e);
    }
#pragma unroll
    for (int off = 4; off > 0; off >>= 1)
        Z += __shfl_xor_sync(0xffffffffu, Z, off, 8);
    if (lane == 0) g_w2z[b * NN + m] = make_float2(wh2m, 1.f / Z);
}

// ---------------------------------------------------------------------------
// Kernel 3: h_prime[b,n,:] = sum_m w(n,m)*Wh[b,m,:]; concat + ELU.
// Block = 512 threads = 64 batches x 8 lanes, one n per block.
// Row list cached in smem; weights broadcast via width-8 shfl.
// ---------------------------------------------------------------------------
__global__ __launch_bounds__(512) void k_out(float* __restrict__ out) {
    const int n    = blockIdx.x;
    const int tid  = threadIdx.x;
    const int b    = tid >> 3;        // 0..63
    const int lane = tid & 7;
    const int cnt  = g_row_cnt[n];

    __shared__ int smi[128];
    if (tid < 128 && tid < cnt) smi[tid] = g_row_idx[n * NN + tid];
    __syncthreads();

    const float wh1n = g_Wh1[b * NN + n];
    const char* whb = (const char*)g_Whh + (size_t)b * NN * 128 + lane * 16;

    float acc[8];
#pragma unroll
    for (int k = 0; k < 8; k++) acc[k] = 0.f;

    for (int k0 = 0; k0 < cnt; k0 += 8) {
        int k = k0 + lane;
        float w = 0.f; int off = 0;
        if (k < cnt) {
            int m = smi[k];
            float2 wz = g_w2z[b * NN + m];
            float s = wh1n + wz.x;
            float e = (s > 0.f) ? s : 0.2f * s;
            w   = __expf(e) * wz.y;
            off = m << 7;             // byte offset: m * 64 ch * 2B
        }
        const int lim = min(8, cnt - k0);
#pragma unroll
        for (int j = 0; j < 8; j++) {
            if (j >= lim) break;
            float wj  = __shfl_sync(0xffffffffu, w,   j, 8);
            int   oj  = __shfl_sync(0xffffffffu, off, j, 8);
            uint4 raw = *(const uint4*)(whb + oj);
            float2 f0 = __half22float2(*(const __half2*)&raw.x);
            float2 f1 = __half22float2(*(const __half2*)&raw.y);
            float2 f2 = __half22float2(*(const __half2*)&raw.z);
            float2 f3 = __half22float2(*(const __half2*)&raw.w);
            acc[0] = fmaf(wj, f0.x, acc[0]); acc[1] = fmaf(wj, f0.y, acc[1]);
            acc[2] = fmaf(wj, f1.x, acc[2]); acc[3] = fmaf(wj, f1.y, acc[3]);
            acc[4] = fmaf(wj, f2.x, acc[4]); acc[5] = fmaf(wj, f2.y, acc[5]);
            acc[6] = fmaf(wj, f3.x, acc[6]); acc[7] = fmaf(wj, f3.y, acc[7]);
        }
    }

#pragma unroll
    for (int k = 0; k < 8; k++) acc[k] = (acc[k] > 0.f) ? acc[k] : expm1f(acc[k]);

    size_t ob = (n < NROW) ? (((size_t)b * NROW + n) * 128 + lane * 8)
                           : (((size_t)b * NROW + (n - NROW)) * 128 + 64 + lane * 8);
    *(float4*)(out + ob)     = make_float4(acc[0], acc[1], acc[2], acc[3]);
    *(float4*)(out + ob + 4) = make_float4(acc[4], acc[5], acc[6], acc[7]);
}

// ---------------------------------------------------------------------------
extern "C" void kernel_launch(void* const* d_in, const int* in_sizes, int n_in,
                              void* d_out, int out_size) {
    const float* h   = (const float*)d_in[0];
    const float* ht  = (const float*)d_in[1];
    const float* W   = (const float*)d_in[2];
    const float* a   = (const float*)d_in[3];
    const float* adj = (const float*)d_in[4];
    float* out = (float*)d_out;

    k_csr<<<dim3((NN + 31) / 32, 2), 1024>>>(adj);
    k_wh<<<dim3((NN + 63) / 64, BATCH), 128>>>(h, ht, W, a);
    k_colstats<<<dim3((NN + 15) / 16, BATCH), 128>>>();
    k_out<<<dim3(NN, 1), 512>>>(out);
}